// round 17
// baseline (speedup 1.0000x reference)
#include <cuda_runtime.h>
#include <cuda_bf16.h>
#include <math.h>

#define N_NODES_MAX 100000
#define N_EDGES_MAX 3200000
#define D 64
#define NL 3
#define SCAN_B 256
#define MAX_NB ((N_NODES_MAX + SCAN_B - 1) / SCAN_B + 1)

// ---- device scratch (no allocation allowed). 256B-aligned for vector loads. ----
__device__ __align__(256) float4 g_edges[N_EDGES_MAX];   // {src, w_l0, w_l1, w_l2}
__device__ __align__(256) int   g_deg[N_NODES_MAX];
__device__ __align__(256) int   g_offs[N_NODES_MAX + 1];
__device__ __align__(256) int   g_cur[N_NODES_MAX];
__device__ __align__(256) int   g_bsum[MAX_NB];
__device__ __align__(256) int   g_boff[MAX_NB];
__device__ __align__(256) float g_ga[(size_t)N_NODES_MAX * D];   // corrected activations
__device__ __align__(256) float g_hA[(size_t)N_NODES_MAX * D];
__device__ __align__(256) float g_hB[(size_t)N_NODES_MAX * D];
__device__ __align__(256) __nv_bfloat16 g_xb [(size_t)N_NODES_MAX * D];
__device__ __align__(256) __nv_bfloat16 g_hbA[(size_t)N_NODES_MAX * D];
__device__ __align__(256) __nv_bfloat16 g_hbB[(size_t)N_NODES_MAX * D];
__device__ int g_is64;

// ---------------------------------------------------------------------------
// Kernel 1: init — zero deg; convert x -> bf16 shadow; block 0 probes dtype.
// ---------------------------------------------------------------------------
__global__ void init_kernel(const int* __restrict__ w32,
                            const float* __restrict__ x,
                            __nv_bfloat16* __restrict__ xb,
                            int N, int nfeat)
{
    int i = blockIdx.x * blockDim.x + threadIdx.x;
    if (i < N) g_deg[i] = 0;

    int idx = i * 4;
    if (idx < nfeat) {
        float4 v = *(const float4*)(x + idx);
        *(__nv_bfloat162*)(xb + idx)     = __floats2bfloat162_rn(v.x, v.y);
        *(__nv_bfloat162*)(xb + idx + 2) = __floats2bfloat162_rn(v.z, v.w);
    }

    if (blockIdx.x == 0) {
        __shared__ int any;
        if (threadIdx.x == 0) any = 0;
        __syncthreads();
        int acc = 0;
        for (int k = threadIdx.x * 2 + 1; k < 4096; k += blockDim.x * 2)
            acc |= w32[k];
        if (acc) atomicOr(&any, 1);
        __syncthreads();
        if (threadIdx.x == 0) g_is64 = (any == 0) ? 1 : 0;
    }
}

// ---------------------------------------------------------------------------
// Kernel 2: in-degree histogram. 4 edges/thread -> 4 independent atomics
// in flight (hide ATOMG latency).
// ---------------------------------------------------------------------------
__global__ void hist_kernel(const void* __restrict__ eidx_raw, int E)
{
    int t = blockIdx.x * blockDim.x + threadIdx.x;
    int e0 = t * 4;
    if (e0 >= E) return;

    int d[4];
    int n = min(4, E - e0);
    if (g_is64) {
        const long long* p = (const long long*)eidx_raw + (size_t)E + e0;
#pragma unroll
        for (int j = 0; j < 4; j++) d[j] = (j < n) ? (int)p[j] : 0;
    } else {
        const int* p = (const int*)eidx_raw + (size_t)E + e0;
#pragma unroll
        for (int j = 0; j < 4; j++) d[j] = (j < n) ? p[j] : 0;
    }
#pragma unroll
    for (int j = 0; j < 4; j++)
        if (j < n) atomicAdd(&g_deg[d[j]], 1);
}

// ---------------------------------------------------------------------------
__global__ void scan_phase1(int N)
{
    __shared__ int sh[SCAN_B];
    const int tid = threadIdx.x;
    const int i = blockIdx.x * SCAN_B + tid;
    int v = (i < N) ? g_deg[i] : 0;
    sh[tid] = v;
    __syncthreads();
    for (int off = 1; off < SCAN_B; off <<= 1) {
        int a = sh[tid];
        int b = (tid >= off) ? sh[tid - off] : 0;
        __syncthreads();
        sh[tid] = a + b;
        __syncthreads();
    }
    if (i < N) g_offs[i] = sh[tid] - v;
    if (tid == SCAN_B - 1) g_bsum[blockIdx.x] = sh[SCAN_B - 1];
}

__global__ void scan_phase2(int NB)
{
    __shared__ int sh[1024];
    const int tid = threadIdx.x;
    int v = (tid < NB) ? g_bsum[tid] : 0;
    sh[tid] = v;
    __syncthreads();
    for (int off = 1; off < 1024; off <<= 1) {
        int a = sh[tid];
        int b = (tid >= off) ? sh[tid - off] : 0;
        __syncthreads();
        sh[tid] = a + b;
        __syncthreads();
    }
    if (tid < NB) g_boff[tid] = sh[tid] - v;
}

__global__ void scan_phase3(int N)
{
    const int i = blockIdx.x * SCAN_B + threadIdx.x;
    if (i < N) {
        int o = g_offs[i] + g_boff[blockIdx.x];
        g_offs[i] = o;
        g_cur[i]  = o;
        if (i == N - 1) g_offs[N] = o + g_deg[i];
    }
}

// ---------------------------------------------------------------------------
// Kernel 4: edge placement. 4 edges/thread: batched index+attr loads, then
// 4 independent atomics + stores in flight.
// ---------------------------------------------------------------------------
__global__ void place_kernel(const void* __restrict__ eidx_raw,
                             const float* __restrict__ eattr,
                             const float* __restrict__ emlp_w,
                             const float* __restrict__ emlp_b,
                             int E)
{
    int t = blockIdx.x * blockDim.x + threadIdx.x;
    int e0 = t * 4;
    if (e0 >= E) return;
    int n = min(4, E - e0);

    int s[4], d[4];
    if (g_is64) {
        const long long* ps = (const long long*)eidx_raw + e0;
        const long long* pd = (const long long*)eidx_raw + (size_t)E + e0;
#pragma unroll
        for (int j = 0; j < 4; j++) {
            s[j] = (j < n) ? (int)ps[j] : 0;
            d[j] = (j < n) ? (int)pd[j] : 0;
        }
    } else {
        const int* ps = (const int*)eidx_raw + e0;
        const int* pd = (const int*)eidx_raw + (size_t)E + e0;
#pragma unroll
        for (int j = 0; j < 4; j++) {
            s[j] = (j < n) ? ps[j] : 0;
            d[j] = (j < n) ? pd[j] : 0;
        }
    }

    float4 a0[4], a1[4];
#pragma unroll
    for (int j = 0; j < 4; j++) {
        size_t e = (size_t)(e0 + ((j < n) ? j : 0));
        a0[j] = *(const float4*)(eattr + e * 8);
        a1[j] = *(const float4*)(eattr + e * 8 + 4);
    }

    float w8[8];
#pragma unroll
    for (int k = 0; k < 8; k++) w8[k] = 0.f;   // placate compiler
    float wl[NL][4];
#pragma unroll
    for (int l = 0; l < NL; l++) {
        const float* wp = emlp_w + l * 8;
        float b = emlp_b[l];
#pragma unroll
        for (int k = 0; k < 8; k++) w8[k] = wp[k];
#pragma unroll
        for (int j = 0; j < 4; j++) {
            float z = b;
            z = fmaf(a0[j].x, w8[0], z);
            z = fmaf(a0[j].y, w8[1], z);
            z = fmaf(a0[j].z, w8[2], z);
            z = fmaf(a0[j].w, w8[3], z);
            z = fmaf(a1[j].x, w8[4], z);
            z = fmaf(a1[j].y, w8[5], z);
            z = fmaf(a1[j].z, w8[6], z);
            z = fmaf(a1[j].w, w8[7], z);
            wl[l][j] = fmaxf(z, 0.f) + log1pf(expf(-fabsf(z)));
        }
    }

    int pos[4];
#pragma unroll
    for (int j = 0; j < 4; j++)
        if (j < n) pos[j] = atomicAdd(&g_cur[d[j]], 1);
#pragma unroll
    for (int j = 0; j < 4; j++)
        if (j < n)
            g_edges[pos[j]] = make_float4(__int_as_float(s[j]),
                                          wl[0][j], wl[1][j], wl[2][j]);
}

// ---------------------------------------------------------------------------
__device__ __forceinline__ void cvt_fma8(float* acc, uint4 u, float w)
{
    float2 p;
    p = __bfloat1622float2(*reinterpret_cast<__nv_bfloat162*>(&u.x));
    acc[0] = fmaf(w, p.x, acc[0]); acc[1] = fmaf(w, p.y, acc[1]);
    p = __bfloat1622float2(*reinterpret_cast<__nv_bfloat162*>(&u.y));
    acc[2] = fmaf(w, p.x, acc[2]); acc[3] = fmaf(w, p.y, acc[3]);
    p = __bfloat1622float2(*reinterpret_cast<__nv_bfloat162*>(&u.z));
    acc[4] = fmaf(w, p.x, acc[4]); acc[5] = fmaf(w, p.y, acc[5]);
    p = __bfloat1622float2(*reinterpret_cast<__nv_bfloat162*>(&u.w));
    acc[6] = fmaf(w, p.x, acc[6]); acc[7] = fmaf(w, p.y, acc[7]);
}

// ---------------------------------------------------------------------------
// Gather kernel (unchanged from R15, 459us config). Warp per node; fully
// predicated 16-edge passes at MLP=4; minBlocks=5.
// ---------------------------------------------------------------------------
template <int L>
__global__ void __launch_bounds__(256, 5)
gather_kernel(const float* __restrict__ hin,
              const __nv_bfloat16* __restrict__ hin_b,
              float* __restrict__ ga, int N)
{
    const int warp = threadIdx.x >> 5;
    const int lane = threadIdx.x & 31;
    const int f8      = lane & 7;
    const int quarter = lane >> 3;
    const int warps_per_grid = (blockDim.x >> 5) * gridDim.x;

    for (int r = blockIdx.x * (blockDim.x >> 5) + warp; r < N; r += warps_per_grid) {
        const int start = __ldg(g_offs + r);
        const int end   = __ldg(g_offs + r + 1);

        float acc[8] = {0.f, 0.f, 0.f, 0.f, 0.f, 0.f, 0.f, 0.f};
        float cw = 0.f;

        for (int i = start + quarter; i < end; i += 16) {
            int i1 = i + 4, i2 = i + 8, i3 = i + 12;
            bool v1 = i1 < end, v2 = i2 < end, v3 = i3 < end;
            int o1 = v1 ? i1 : start;
            int o2 = v2 ? i2 : start;
            int o3 = v3 ? i3 : start;

            float4 r0 = __ldg(g_edges + i);
            float4 r1 = __ldg(g_edges + o1);
            float4 r2 = __ldg(g_edges + o2);
            float4 r3 = __ldg(g_edges + o3);
            uint4 u0 = __ldg((const uint4*)(hin_b + (size_t)__float_as_int(r0.x) * D) + f8);
            uint4 u1 = __ldg((const uint4*)(hin_b + (size_t)__float_as_int(r1.x) * D) + f8);
            uint4 u2 = __ldg((const uint4*)(hin_b + (size_t)__float_as_int(r2.x) * D) + f8);
            uint4 u3 = __ldg((const uint4*)(hin_b + (size_t)__float_as_int(r3.x) * D) + f8);

            float w0 = (L == 0) ? r0.y : (L == 1) ? r0.z : r0.w;
            float w1 = (L == 0) ? r1.y : (L == 1) ? r1.z : r1.w;
            float w2 = (L == 0) ? r2.y : (L == 1) ? r2.z : r2.w;
            float w3 = (L == 0) ? r3.y : (L == 1) ? r3.z : r3.w;
            w1 = v1 ? w1 : 0.f;
            w2 = v2 ? w2 : 0.f;
            w3 = v3 ? w3 : 0.f;

            cvt_fma8(acc, u0, w0); cw += w0;
            cvt_fma8(acc, u1, w1); cw += w1;
            cvt_fma8(acc, u2, w2); cw += w2;
            cvt_fma8(acc, u3, w3); cw += w3;
        }

#pragma unroll
        for (int j = 0; j < 8; j++) {
            acc[j] += __shfl_xor_sync(0xffffffffu, acc[j], 8);
            acc[j] += __shfl_xor_sync(0xffffffffu, acc[j], 16);
        }
#pragma unroll
        for (int o = 16; o > 0; o >>= 1)
            cw += __shfl_xor_sync(0xffffffffu, cw, o);
        cw *= (1.f / 8.f);

        if (lane < 8) {
            const float* hr = hin + (size_t)r * D + f8 * 8;
            float4 h0 = *(const float4*)hr;
            float4 h1 = *(const float4*)(hr + 4);
            float4 o0 = make_float4(acc[0] - cw * h0.x, acc[1] - cw * h0.y,
                                    acc[2] - cw * h0.z, acc[3] - cw * h0.w);
            float4 o1 = make_float4(acc[4] - cw * h1.x, acc[5] - cw * h1.y,
                                    acc[6] - cw * h1.z, acc[7] - cw * h1.w);
            float* gp = ga + (size_t)r * D + f8 * 8;
            *(float4*)gp       = o0;
            *(float4*)(gp + 4) = o1;
        }
    }
}

// ---------------------------------------------------------------------------
// Node-update kernel: register-tiled GEMM over 64-node tiles (unchanged).
// ---------------------------------------------------------------------------
template <bool FUSE_FC>
__global__ void __launch_bounds__(256)
nodeupdate_kernel(const float* __restrict__ ga,
                  const float* __restrict__ hin,
                  float* __restrict__ hout,
                  __nv_bfloat16* __restrict__ hout_b,   // null if FUSE_FC
                  const float* __restrict__ W,
                  const float* __restrict__ bias,
                  const float* __restrict__ gamma,
                  const float* __restrict__ beta,
                  const float* __restrict__ fcW,
                  const float* __restrict__ fcb,
                  int N)
{
    __shared__ float sAT[D][72];
    __shared__ float sWT[D][68];
    __shared__ float sred[D][34];
    __shared__ float smu[D], sinv[D];
    __shared__ float sb[D], sg[D], sbt[D], sfb[D];

    const int tid = threadIdx.x;

    for (int i = tid; i < D * D; i += 256) {
        int row = i >> 6, k = i & 63;
        sWT[k][row] = W[i];
    }
    if (tid < D) {
        sb[tid]  = bias[tid];
        sg[tid]  = gamma[tid];
        sbt[tid] = beta[tid];
        if (FUSE_FC) sfb[tid] = fcb[tid];
    }

    const int base = blockIdx.x * 64;
    {
        int node_l = tid >> 2, kq = tid & 3;
        int node = base + node_l;
#pragma unroll
        for (int q = 0; q < 4; q++) {
            int k0 = kq * 16 + q * 4;
            float4 v = make_float4(0.f, 0.f, 0.f, 0.f);
            if (node < N) v = *(const float4*)(ga + (size_t)node * D + k0);
            sAT[k0][node_l]     = v.x;
            sAT[k0 + 1][node_l] = v.y;
            sAT[k0 + 2][node_l] = v.z;
            sAT[k0 + 3][node_l] = v.w;
        }
    }
    __syncthreads();

    const int tn = tid & 15, tc = tid >> 4;

    float acc[4][4] = {};
#pragma unroll
    for (int k = 0; k < D; k++) {
        float4 a4 = *(const float4*)&sAT[k][tn * 4];
        float4 w4 = *(const float4*)&sWT[k][tc * 4];
        float aa[4] = {a4.x, a4.y, a4.z, a4.w};
        float ww[4] = {w4.x, w4.y, w4.z, w4.w};
#pragma unroll
        for (int ni = 0; ni < 4; ni++)
#pragma unroll
            for (int ci = 0; ci < 4; ci++)
                acc[ni][ci] = fmaf(aa[ni], ww[ci], acc[ni][ci]);
    }

    float h[4][4];
#pragma unroll
    for (int ni = 0; ni < 4; ni++) {
        float s = 0.f, sq = 0.f;
#pragma unroll
        for (int ci = 0; ci < 4; ci++) {
            float v = fmaxf(acc[ni][ci] + sb[tc * 4 + ci], 0.f);
            h[ni][ci] = v;
            s += v;
            sq += v * v;
        }
        sred[tn * 4 + ni][tc]      = s;
        sred[tn * 4 + ni][17 + tc] = sq;
    }
    __syncthreads();

    if (tid < 64) {
        float s = 0.f, sq = 0.f;
#pragma unroll
        for (int j = 0; j < 16; j++) {
            s  += sred[tid][j];
            sq += sred[tid][17 + j];
        }
        float mu  = s * (1.f / D);
        float var = sq * (1.f / D) - mu * mu;
        smu[tid]  = mu;
        sinv[tid] = rsqrtf(var + 1e-5f);
    }
    __syncthreads();

    float o[4][4];
#pragma unroll
    for (int ni = 0; ni < 4; ni++) {
        int node = base + tn * 4 + ni;
        float4 hi = make_float4(0.f, 0.f, 0.f, 0.f);
        if (node < N) hi = *(const float4*)(hin + (size_t)node * D + tc * 4);
        float hiv[4] = {hi.x, hi.y, hi.z, hi.w};
        float mu  = smu[tn * 4 + ni];
        float inv = sinv[tn * 4 + ni];
#pragma unroll
        for (int ci = 0; ci < 4; ci++) {
            int col = tc * 4 + ci;
            o[ni][ci] = (h[ni][ci] - mu) * inv * sg[col] + sbt[col] + hiv[ci];
        }
    }

    if (!FUSE_FC) {
#pragma unroll
        for (int ni = 0; ni < 4; ni++) {
            int node = base + tn * 4 + ni;
            if (node < N) {
                float* hp = hout + (size_t)node * D + tc * 4;
                *(float4*)hp = make_float4(o[ni][0], o[ni][1], o[ni][2], o[ni][3]);
                __nv_bfloat16* bp = hout_b + (size_t)node * D + tc * 4;
                *(__nv_bfloat162*)bp       = __floats2bfloat162_rn(o[ni][0], o[ni][1]);
                *(__nv_bfloat162*)(bp + 2) = __floats2bfloat162_rn(o[ni][2], o[ni][3]);
            }
        }
    } else {
        for (int i = tid; i < D * D; i += 256) {
            int row = i >> 6, k = i & 63;
            sWT[k][row] = fcW[i];
        }
#pragma unroll
        for (int ni = 0; ni < 4; ni++)
#pragma unroll
            for (int ci = 0; ci < 4; ci++)
                sAT[tc * 4 + ci][tn * 4 + ni] = o[ni][ci];
        __syncthreads();

        float f[4][4] = {};
#pragma unroll
        for (int k = 0; k < D; k++) {
            float4 a4 = *(const float4*)&sAT[k][tn * 4];
            float4 w4 = *(const float4*)&sWT[k][tc * 4];
            float aa[4] = {a4.x, a4.y, a4.z, a4.w};
            float ww[4] = {w4.x, w4.y, w4.z, w4.w};
#pragma unroll
            for (int ni = 0; ni < 4; ni++)
#pragma unroll
                for (int ci = 0; ci < 4; ci++)
                    f[ni][ci] = fmaf(aa[ni], ww[ci], f[ni][ci]);
        }
#pragma unroll
        for (int ni = 0; ni < 4; ni++) {
            int node = base + tn * 4 + ni;
            if (node < N) {
                float* hp = hout + (size_t)node * D + tc * 4;
                *(float4*)hp = make_float4(f[ni][0] + sfb[tc * 4 + 0],
                                           f[ni][1] + sfb[tc * 4 + 1],
                                           f[ni][2] + sfb[tc * 4 + 2],
                                           f[ni][3] + sfb[tc * 4 + 3]);
            }
        }
    }
}

// ---------------------------------------------------------------------------
extern "C" void kernel_launch(void* const* d_in, const int* in_sizes, int n_in,
                              void* d_out, int out_size)
{
    const float* x      = (const float*)d_in[0];
    const void*  eidx   = d_in[1];
    const float* eattr  = (const float*)d_in[2];
    const float* lin_w  = (const float*)d_in[3];
    const float* lin_b  = (const float*)d_in[4];
    const float* emlp_w = (const float*)d_in[5];
    const float* emlp_b = (const float*)d_in[6];
    const float* gamma  = (const float*)d_in[7];
    const float* beta   = (const float*)d_in[8];
    const float* fc_w   = (const float*)d_in[9];
    const float* fc_b   = (const float*)d_in[10];
    float*       out    = (float*)d_out;

    const int E = in_sizes[1] / 2;
    const int N = in_sizes[0] / D;

    float *hA, *hB, *ga;
    __nv_bfloat16 *xb, *hbA, *hbB;
    cudaGetSymbolAddress((void**)&hA,  g_hA);
    cudaGetSymbolAddress((void**)&hB,  g_hB);
    cudaGetSymbolAddress((void**)&ga,  g_ga);
    cudaGetSymbolAddress((void**)&xb,  g_xb);
    cudaGetSymbolAddress((void**)&hbA, g_hbA);
    cudaGetSymbolAddress((void**)&hbB, g_hbB);

    // --- build ---
    const int NB = (N + SCAN_B - 1) / SCAN_B;
    const int nfeat = N * D;
    const int init_blocks = (nfeat / 4 + 255) / 256;
    const int e4 = (E + 3) / 4;
    init_kernel<<<init_blocks, 256>>>((const int*)eidx, x, xb, N, nfeat);
    hist_kernel<<<(e4 + 255) / 256, 256>>>(eidx, E);
    scan_phase1<<<NB, SCAN_B>>>(N);
    scan_phase2<<<1, 1024>>>(NB);
    scan_phase3<<<NB, SCAN_B>>>(N);
    place_kernel<<<(e4 + 255) / 256, 256>>>(eidx, eattr, emlp_w, emlp_b, E);

    // --- layers: gather -> tiled GEMM/LN/residual ---
    const int gblocks = 2960, gthreads = 256;
    const int tblocks = (N + 63) / 64;

    gather_kernel<0><<<gblocks, gthreads>>>(x, xb, ga, N);
    nodeupdate_kernel<false><<<tblocks, 256>>>(ga, x, hA, hbA,
                                               lin_w, lin_b, gamma, beta,
                                               nullptr, nullptr, N);

    gather_kernel<1><<<gblocks, gthreads>>>(hA, hbA, ga, N);
    nodeupdate_kernel<false><<<tblocks, 256>>>(ga, hA, hB, hbB,
                                               lin_w + (size_t)D * D, lin_b + D,
                                               gamma + D, beta + D,
                                               nullptr, nullptr, N);

    gather_kernel<2><<<gblocks, gthreads>>>(hB, hbB, ga, N);
    nodeupdate_kernel<true><<<tblocks, 256>>>(ga, hB, out, nullptr,
                                              lin_w + (size_t)2 * D * D, lin_b + 2 * D,
                                              gamma + 2 * D, beta + 2 * D,
                                              fc_w, fc_b, N);
}